// round 1
// baseline (speedup 1.0000x reference)
#include <cuda_runtime.h>
#include <cuda_bf16.h>

#define S 1024
#define B 8192
#define EPSF 1e-8f
#define WARPS_PER_BLOCK 8
#define THREADS 256

// One warp per batch row. Reverse affine scan ret_t = a_t*ret_{t+1} + b_t,
// processed in chunks of 32 timesteps via warp suffix-composition scan.
// Last block computes the lambda-weight sequence + normalization (srw).
__global__ void td_lambda_kernel(const float* __restrict__ raw_gamma,
                                 const float* __restrict__ raw_lambd,
                                 const float* __restrict__ values,
                                 const float* __restrict__ rewards,
                                 const int*   __restrict__ dones,
                                 float* __restrict__ out)
{
    __shared__ float s_lam[S];
    const int tid = threadIdx.x;
    const float gamma = fmaxf(tanhf(raw_gamma[0]), EPSF);

    // lambda = max(tanh(raw_lambd), eps), shared per block
    for (int i = tid; i < S; i += THREADS)
        s_lam[i] = fmaxf(tanhf(raw_lambd[i]), EPSF);
    __syncthreads();

    const int lane = tid & 31;

    if (blockIdx.x < B / WARPS_PER_BLOCK) {
        // ---------------- main per-row scan ----------------
        const int warp = tid >> 5;
        const int b = blockIdx.x * WARPS_PER_BLOCK + warp;
        const float* __restrict__ rrow = rewards + (size_t)b * S;
        const int*   __restrict__ drow = dones   + (size_t)b * S;
        const float* __restrict__ vrow = values  + (size_t)b * (S + 1);
        float* __restrict__ orow = out + (size_t)b * S;

        float carry = __ldg(&vrow[S]);   // ret_{S} = values[:, -1]

        #pragma unroll 1
        for (int c = S / 32 - 1; c >= 0; --c) {
            const int t = c * 32 + lane;
            // coalesced loads along t
            float r   = rrow[t];
            float dn  = (float)drow[t];
            float vn  = vrow[t + 1];
            float lam = s_lam[t];

            float g1d = gamma * (1.0f - dn);
            float a   = g1d * lam;                       // multiplier
            float bb  = fmaf(g1d * (1.0f - lam), vn, r); // offset

            // suffix inclusive scan: lane i gets F_i ∘ F_{i+1} ∘ ... ∘ F_31
            #pragma unroll
            for (int off = 1; off < 32; off <<= 1) {
                float a2 = __shfl_down_sync(0xffffffffu, a,  off);
                float b2 = __shfl_down_sync(0xffffffffu, bb, off);
                if (lane + off < 32) {
                    bb = fmaf(a, b2, bb);
                    a  = a * a2;
                }
            }

            float ret = fmaf(a, carry, bb);   // ret_{t}
            orow[t] = ret;                    // coalesced store
            carry = __shfl_sync(0xffffffffu, ret, 0);  // ret at t = c*32
        }
    } else {
        // ---------------- srw (sum_reward_weights) ----------------
        __shared__ float s_w[S];
        __shared__ float s_part[THREADS];

        if (tid < 32) {
            // v_t = gamma*(1-lam_t) + gamma*lam_t*v_{t+1}, v_S = 1
            float carry = 1.0f;
            for (int c = S / 32 - 1; c >= 0; --c) {
                const int t = c * 32 + lane;
                float lam = s_lam[t];
                float a  = gamma * lam;
                float bb = gamma * (1.0f - lam);
                #pragma unroll
                for (int off = 1; off < 32; off <<= 1) {
                    float a2 = __shfl_down_sync(0xffffffffu, a,  off);
                    float b2 = __shfl_down_sync(0xffffffffu, bb, off);
                    if (lane + off < 32) {
                        bb = fmaf(a, b2, bb);
                        a  = a * a2;
                    }
                }
                float v = fmaf(a, carry, bb);
                s_w[t] = fmaxf(1.0f - v, EPSF);
                carry = __shfl_sync(0xffffffffu, v, 0);
            }
        }
        __syncthreads();

        // mean(w)
        float ps = 0.0f;
        for (int i = tid; i < S; i += THREADS) ps += s_w[i];
        s_part[tid] = ps;
        __syncthreads();
        for (int stride = THREADS / 2; stride > 0; stride >>= 1) {
            if (tid < stride) s_part[tid] += s_part[tid + stride];
            __syncthreads();
        }
        float mean = s_part[0] * (1.0f / (float)S);
        float inv  = 1.0f / fmaxf(mean, EPSF);
        for (int i = tid; i < S; i += THREADS)
            out[(size_t)B * S + i] = s_w[i] * inv;
    }
}

extern "C" void kernel_launch(void* const* d_in, const int* in_sizes, int n_in,
                              void* d_out, int out_size) {
    const float* raw_gamma = (const float*)d_in[0];
    const float* raw_lambd = (const float*)d_in[1];
    const float* values    = (const float*)d_in[2];
    const float* rewards   = (const float*)d_in[3];
    const int*   dones     = (const int*)d_in[4];
    float* out = (float*)d_out;

    const int grid = B / WARPS_PER_BLOCK + 1;   // 1024 row-blocks + 1 srw block
    td_lambda_kernel<<<grid, THREADS>>>(raw_gamma, raw_lambd, values, rewards, dones, out);
}

// round 2
// speedup vs baseline: 1.1294x; 1.1294x over previous
#include <cuda_runtime.h>
#include <cuda_bf16.h>

#define S 1024
#define B 8192
#define EPSF 1e-8f
#define WARPS_PER_BLOCK 8
#define THREADS 256
#define LPT 8                 // timesteps per lane
#define CHUNK (32 * LPT)      // 256 timesteps per warp-scan
#define NCHUNK (S / CHUNK)    // 4

// One warp per batch row. Reverse affine scan ret_t = a_t*ret_{t+1} + b_t.
// Each lane composes 8 consecutive steps locally (FMA only), one 5-stage
// warp suffix-scan combines the 32 lane-composites, then each lane replays
// its 8 outputs sequentially. 8x fewer shuffles than 1-step-per-lane.
__global__ void td_lambda_kernel(const float* __restrict__ raw_gamma,
                                 const float* __restrict__ raw_lambd,
                                 const float* __restrict__ values,
                                 const float* __restrict__ rewards,
                                 const int*   __restrict__ dones,
                                 float* __restrict__ out)
{
    __shared__ float s_lam[S];
    const int tid = threadIdx.x;
    const float gamma = fmaxf(tanhf(raw_gamma[0]), EPSF);

    for (int i = tid; i < S; i += THREADS)
        s_lam[i] = fmaxf(tanhf(raw_lambd[i]), EPSF);
    __syncthreads();

    const int lane = tid & 31;

    if (blockIdx.x < B / WARPS_PER_BLOCK) {
        const int warp = tid >> 5;
        const int b = blockIdx.x * WARPS_PER_BLOCK + warp;
        const float* __restrict__ rrow = rewards + (size_t)b * S;
        const int*   __restrict__ drow = dones   + (size_t)b * S;
        const float* __restrict__ vrow = values  + (size_t)b * (S + 1);
        float* __restrict__ orow = out + (size_t)b * S;

        float carry = __ldg(&vrow[S]);   // ret_S

        #pragma unroll
        for (int c = NCHUNK - 1; c >= 0; --c) {
            const int base = c * CHUNK + lane * LPT;

            // ---- vectorized loads (lane-contiguous) ----
            float4 rv0 = *(const float4*)(rrow + base);
            float4 rv1 = *(const float4*)(rrow + base + 4);
            int4   dv0 = *(const int4*)(drow + base);
            int4   dv1 = *(const int4*)(drow + base + 4);
            float r[LPT] = {rv0.x, rv0.y, rv0.z, rv0.w, rv1.x, rv1.y, rv1.z, rv1.w};
            int   dn[LPT] = {dv0.x, dv0.y, dv0.z, dv0.w, dv1.x, dv1.y, dv1.z, dv1.w};
            float v[LPT], lam[LPT];
            #pragma unroll
            for (int j = 0; j < LPT; ++j) v[j] = vrow[base + j + 1];
            #pragma unroll
            for (int j = 0; j < LPT; ++j) lam[j] = s_lam[base + j];

            // ---- per-step affine coeffs ----
            float a[LPT], bb[LPT];
            #pragma unroll
            for (int j = 0; j < LPT; ++j) {
                float g1d = (dn[j] != 0) ? 0.0f : gamma;
                a[j]  = g1d * lam[j];
                bb[j] = fmaf(g1d * (1.0f - lam[j]), v[j], r[j]);
            }

            // ---- local composition: G = F_{j0} ∘ ... ∘ F_{j7} ----
            float A = a[LPT - 1], Bc = bb[LPT - 1];
            #pragma unroll
            for (int j = LPT - 2; j >= 0; --j) {
                Bc = fmaf(a[j], Bc, bb[j]);
                A  = a[j] * A;
            }

            // ---- inclusive warp suffix-scan of lane composites ----
            // lane i ends with I_i = G_i ∘ G_{i+1} ∘ ... ∘ G_31
            float sA = A, sB = Bc;
            #pragma unroll
            for (int off = 1; off < 32; off <<= 1) {
                float a2 = __shfl_down_sync(0xffffffffu, sA, off);
                float b2 = __shfl_down_sync(0xffffffffu, sB, off);
                if (lane + off < 32) {
                    sB = fmaf(sA, b2, sB);
                    sA = sA * a2;
                }
            }

            // entry value for this lane's segment: I_{i+1}(carry); lane31 -> carry
            float eA = __shfl_down_sync(0xffffffffu, sA, 1);
            float eB = __shfl_down_sync(0xffffffffu, sB, 1);
            if (lane == 31) { eA = 1.0f; eB = 0.0f; }
            float x = fmaf(eA, carry, eB);

            // new chunk carry = I_0(carry)
            float cA = __shfl_sync(0xffffffffu, sA, 0);
            float cB = __shfl_sync(0xffffffffu, sB, 0);

            // ---- sequential replay of 8 outputs ----
            float o[LPT];
            #pragma unroll
            for (int j = LPT - 1; j >= 0; --j) {
                x = fmaf(a[j], x, bb[j]);
                o[j] = x;
            }
            *(float4*)(orow + base)     = make_float4(o[0], o[1], o[2], o[3]);
            *(float4*)(orow + base + 4) = make_float4(o[4], o[5], o[6], o[7]);

            carry = fmaf(cA, carry, cB);
        }
    } else {
        // ---------------- srw (sum_reward_weights) ----------------
        __shared__ float s_w[S];
        __shared__ float s_part[THREADS];

        if (tid < 32) {
            float carry = 1.0f;
            for (int c = S / 32 - 1; c >= 0; --c) {
                const int t = c * 32 + lane;
                float lam = s_lam[t];
                float a  = gamma * lam;
                float bb = gamma * (1.0f - lam);
                #pragma unroll
                for (int off = 1; off < 32; off <<= 1) {
                    float a2 = __shfl_down_sync(0xffffffffu, a,  off);
                    float b2 = __shfl_down_sync(0xffffffffu, bb, off);
                    if (lane + off < 32) {
                        bb = fmaf(a, b2, bb);
                        a  = a * a2;
                    }
                }
                float vv = fmaf(a, carry, bb);
                s_w[t] = fmaxf(1.0f - vv, EPSF);
                carry = __shfl_sync(0xffffffffu, vv, 0);
            }
        }
        __syncthreads();

        float ps = 0.0f;
        for (int i = tid; i < S; i += THREADS) ps += s_w[i];
        s_part[tid] = ps;
        __syncthreads();
        for (int stride = THREADS / 2; stride > 0; stride >>= 1) {
            if (tid < stride) s_part[tid] += s_part[tid + stride];
            __syncthreads();
        }
        float mean = s_part[0] * (1.0f / (float)S);
        float inv  = 1.0f / fmaxf(mean, EPSF);
        for (int i = tid; i < S; i += THREADS)
            out[(size_t)B * S + i] = s_w[i] * inv;
    }
}

extern "C" void kernel_launch(void* const* d_in, const int* in_sizes, int n_in,
                              void* d_out, int out_size) {
    const float* raw_gamma = (const float*)d_in[0];
    const float* raw_lambd = (const float*)d_in[1];
    const float* values    = (const float*)d_in[2];
    const float* rewards   = (const float*)d_in[3];
    const int*   dones     = (const int*)d_in[4];
    float* out = (float*)d_out;

    const int grid = B / WARPS_PER_BLOCK + 1;
    td_lambda_kernel<<<grid, THREADS>>>(raw_gamma, raw_lambd, values, rewards, dones, out);
}

// round 3
// speedup vs baseline: 1.2626x; 1.1179x over previous
#include <cuda_runtime.h>
#include <cuda_bf16.h>

#define S 1024
#define B 8192
#define EPSF 1e-8f
#define WPB 8
#define THREADS 256
#define LPT 8
#define CHUNK 256
#define NCHUNK 4

// padded index: bank-conflict-free for both stride-1 and stride-8 access
__device__ __forceinline__ int padi(int i) { return i + (i >> 5); }

__global__ __launch_bounds__(THREADS)
void td_lambda_kernel(const float* __restrict__ raw_gamma,
                      const float* __restrict__ raw_lambd,
                      const float* __restrict__ values,
                      const float* __restrict__ rewards,
                      const int*   __restrict__ dones,
                      float* __restrict__ out)
{
    __shared__ float s_ga[S + S / 32];   // gamma*lam  (padded)
    __shared__ float s_gb[S + S / 32];   // gamma*(1-lam)
    __shared__ float s_v[WPB][2][CHUNK + CHUNK / 32];  // staged values, double-buffered

    const int tid  = threadIdx.x;
    const int lane = tid & 31;
    const int warp = tid >> 5;
    const float gamma = fmaxf(tanhf(raw_gamma[0]), EPSF);

    for (int i = tid; i < S; i += THREADS) {
        float lam = fmaxf(tanhf(raw_lambd[i]), EPSF);
        s_ga[padi(i)] = gamma * lam;
        s_gb[padi(i)] = gamma * (1.0f - lam);
    }
    __syncthreads();

    if (blockIdx.x < B / WPB) {
        const int b = blockIdx.x * WPB + warp;
        const float* __restrict__ rrow = rewards + (size_t)b * S;
        const int*   __restrict__ drow = dones   + (size_t)b * S;
        const float* __restrict__ vrow = values  + (size_t)b * (S + 1);
        float* __restrict__ orow = out + (size_t)b * S;

        float carry = __ldg(&vrow[S]);

        // ---- prologue: load chunk NCHUNK-1 ----
        float4 r0, r1; int4 d0, d1; float vv[8];
        {
            const int cb = (NCHUNK - 1) * CHUNK;
            r0 = *(const float4*)(rrow + cb + lane * LPT);
            r1 = *(const float4*)(rrow + cb + lane * LPT + 4);
            d0 = *(const int4*)(drow + cb + lane * LPT);
            d1 = *(const int4*)(drow + cb + lane * LPT + 4);
            #pragma unroll
            for (int k = 0; k < 8; ++k)               // coalesced: 32 consecutive floats
                vv[k] = vrow[cb + 1 + lane + 32 * k];
            #pragma unroll
            for (int k = 0; k < 8; ++k)               // padded store: bank = lane
                s_v[warp][(NCHUNK - 1) & 1][lane + 33 * k] = vv[k];
        }
        __syncwarp();

        #pragma unroll
        for (int c = NCHUNK - 1; c >= 0; --c) {
            // ---- issue next chunk's loads early (hidden behind this chunk's scan) ----
            float4 nr0, nr1; int4 nd0, nd1; float nv[8];
            if (c > 0) {
                const int cb = (c - 1) * CHUNK;
                nr0 = *(const float4*)(rrow + cb + lane * LPT);
                nr1 = *(const float4*)(rrow + cb + lane * LPT + 4);
                nd0 = *(const int4*)(drow + cb + lane * LPT);
                nd1 = *(const int4*)(drow + cb + lane * LPT + 4);
                #pragma unroll
                for (int k = 0; k < 8; ++k)
                    nv[k] = vrow[cb + 1 + lane + 32 * k];
            }

            // ---- compute this chunk ----
            const int base = c * CHUNK + lane * LPT;
            float r[LPT]  = {r0.x, r0.y, r0.z, r0.w, r1.x, r1.y, r1.z, r1.w};
            int   dn[LPT] = {d0.x, d0.y, d0.z, d0.w, d1.x, d1.y, d1.z, d1.w};
            const float* vbuf = &s_v[warp][c & 1][0];

            float a[LPT], bb[LPT];
            #pragma unroll
            for (int j = 0; j < LPT; ++j) {
                int t = base + j;
                float ga = s_ga[padi(t)];
                float gb = s_gb[padi(t)];
                float v  = vbuf[lane * LPT + j + (lane >> 2)];  // conflict-free
                bool  z  = (dn[j] != 0);
                a[j]  = z ? 0.0f : ga;
                bb[j] = z ? r[j] : fmaf(gb, v, r[j]);
            }

            // local composition G = F_j0 ∘ ... ∘ F_j7
            float A = a[LPT - 1], Bc = bb[LPT - 1];
            #pragma unroll
            for (int j = LPT - 2; j >= 0; --j) {
                Bc = fmaf(a[j], Bc, bb[j]);
                A  = a[j] * A;
            }

            // warp suffix scan of composites
            float sA = A, sB = Bc;
            #pragma unroll
            for (int off = 1; off < 32; off <<= 1) {
                float a2 = __shfl_down_sync(0xffffffffu, sA, off);
                float b2 = __shfl_down_sync(0xffffffffu, sB, off);
                if (lane + off < 32) {
                    sB = fmaf(sA, b2, sB);
                    sA = sA * a2;
                }
            }

            float eA = __shfl_down_sync(0xffffffffu, sA, 1);
            float eB = __shfl_down_sync(0xffffffffu, sB, 1);
            if (lane == 31) { eA = 1.0f; eB = 0.0f; }
            float x = fmaf(eA, carry, eB);

            float cA = __shfl_sync(0xffffffffu, sA, 0);
            float cB = __shfl_sync(0xffffffffu, sB, 0);

            float o[LPT];
            #pragma unroll
            for (int j = LPT - 1; j >= 0; --j) {
                x = fmaf(a[j], x, bb[j]);
                o[j] = x;
            }
            *(float4*)(orow + base)     = make_float4(o[0], o[1], o[2], o[3]);
            *(float4*)(orow + base + 4) = make_float4(o[4], o[5], o[6], o[7]);

            carry = fmaf(cA, carry, cB);

            // ---- stage next chunk's v, rotate registers ----
            if (c > 0) {
                #pragma unroll
                for (int k = 0; k < 8; ++k)
                    s_v[warp][(c - 1) & 1][lane + 33 * k] = nv[k];
                __syncwarp();
                r0 = nr0; r1 = nr1; d0 = nd0; d1 = nd1;
            }
        }
    } else {
        // ---------------- srw (sum_reward_weights) ----------------
        __shared__ float s_w[S];
        __shared__ float s_part[THREADS];

        if (tid < 32) {
            float carry = 1.0f;
            for (int c = S / 32 - 1; c >= 0; --c) {
                const int t = c * 32 + lane;
                float a  = s_ga[padi(t)];
                float bb = s_gb[padi(t)];
                #pragma unroll
                for (int off = 1; off < 32; off <<= 1) {
                    float a2 = __shfl_down_sync(0xffffffffu, a,  off);
                    float b2 = __shfl_down_sync(0xffffffffu, bb, off);
                    if (lane + off < 32) {
                        bb = fmaf(a, b2, bb);
                        a  = a * a2;
                    }
                }
                float vv = fmaf(a, carry, bb);
                s_w[t] = fmaxf(1.0f - vv, EPSF);
                carry = __shfl_sync(0xffffffffu, vv, 0);
            }
        }
        __syncthreads();

        float ps = 0.0f;
        for (int i = tid; i < S; i += THREADS) ps += s_w[i];
        s_part[tid] = ps;
        __syncthreads();
        for (int stride = THREADS / 2; stride > 0; stride >>= 1) {
            if (tid < stride) s_part[tid] += s_part[tid + stride];
            __syncthreads();
        }
        float mean = s_part[0] * (1.0f / (float)S);
        float inv  = 1.0f / fmaxf(mean, EPSF);
        for (int i = tid; i < S; i += THREADS)
            out[(size_t)B * S + i] = s_w[i] * inv;
    }
}

extern "C" void kernel_launch(void* const* d_in, const int* in_sizes, int n_in,
                              void* d_out, int out_size) {
    const float* raw_gamma = (const float*)d_in[0];
    const float* raw_lambd = (const float*)d_in[1];
    const float* values    = (const float*)d_in[2];
    const float* rewards   = (const float*)d_in[3];
    const int*   dones     = (const int*)d_in[4];
    float* out = (float*)d_out;

    const int grid = B / WPB + 1;
    td_lambda_kernel<<<grid, THREADS>>>(raw_gamma, raw_lambd, values, rewards, dones, out);
}